// round 9
// baseline (speedup 1.0000x reference)
#include <cuda_runtime.h>
#include <math.h>
#include <stdint.h>

#define NN   32768
#define FF   64
#define HH   4
#define HF   256
#define ESZ  524288
#define EGZ  524288
#define GG   64
#define NCLS 10
#define BNEPS 1e-5f

// ---------------- device scratch (static allocation only) ----------------
__device__ float  d_xs[4][NN*FF];      // x0..x3 (GAT inputs)
__device__ float  d_xh[3][NN*FF];      // xh1..xh3 intermediates
__device__ float  d_h[4][NN*HF];       // h_i = xs_i @ W_i
__device__ float  d_as[4][NN*HH];
__device__ float  d_ad[4][NN*HH];
__device__ float  d_gacc[4][NN*HF];    // elu(gat output) per layer
__device__ float  d_z[4][NN*FF];       // mlp output per layer
__device__ float  d_bnpart[4*512*FF*2];
__device__ float  d_bnmu[4][FF];
__device__ float  d_bnrstd[4][FF];
__device__ float  d_pooled[GG*FF];
__device__ float  d_h1[GG*256];
__device__ float  d_h2[GG*128];
// CSR scratch: graphs 0..3 = scatter graphs (packed src+attr), 4 = gat edges
__device__ int    d_cnt[5][2*NN];
__device__ int    d_rowptr[5][NN+1];
__device__ int2   d_cedge[4][ESZ];
__device__ int    d_csrc4[ESZ];

// ---------------- helpers ----------------
__device__ __forceinline__ float lrelu(float x) { return x >= 0.f ? x : 0.2f * x; }
__device__ __forceinline__ float elu(float x)   { return x > 0.f ? x : expm1f(x); }

__device__ __forceinline__ uint32_t f2tf32(float f) {
    uint32_t u;
    asm("cvt.rna.tf32.f32 %0, %1;" : "=r"(u) : "f"(f));
    return u;
}
__device__ __forceinline__ void mma_tf32(float c[4], const uint32_t a[4], const uint32_t b[2]) {
    asm volatile(
        "mma.sync.aligned.m16n8k8.row.col.f32.tf32.tf32.f32 "
        "{%0,%1,%2,%3}, {%4,%5,%6,%7}, {%8,%9}, {%0,%1,%2,%3};"
        : "+f"(c[0]), "+f"(c[1]), "+f"(c[2]), "+f"(c[3])
        : "r"(a[0]), "r"(a[1]), "r"(a[2]), "r"(a[3]), "r"(b[0]), "r"(b[1]));
}

__global__ void zero_i_kernel(int* p, int n) {
    int i = blockIdx.x * blockDim.x + threadIdx.x;
    if (i < n) p[i] = 0;
}
__global__ void zero_f_kernel(float4* p, int n4) {
    int i = blockIdx.x * blockDim.x + threadIdx.x;
    if (i < n4) p[i] = make_float4(0.f, 0.f, 0.f, 0.f);
}

// ---------------- batched CSR build (5 graphs at once) ----------------
__global__ void hist5_kernel(const int* __restrict__ sidx, const int* __restrict__ eidx,
                             int* __restrict__ cnt) {
    int g = blockIdx.y;
    const int* dst = (g < 4) ? (sidx + (size_t)g * 2 * ESZ + ESZ) : (eidx + EGZ);
    int e = blockIdx.x * blockDim.x + threadIdx.x;
    if (e < ESZ) atomicAdd(&cnt[(size_t)g * 2 * NN + dst[e]], 1);
}

__global__ void scan5_kernel(const int* __restrict__ cnt_all, int* __restrict__ rowptr_all) {
    int g = blockIdx.x;
    const int* cnt = cnt_all + (size_t)g * 2 * NN;
    int* rowptr = rowptr_all + (size_t)g * (NN + 1);
    __shared__ int sh[1024];
    int t = threadIdx.x;
    int base = t * 32;
    int local[32];
    int s = 0;
#pragma unroll
    for (int i = 0; i < 32; i++) { local[i] = s; s += cnt[base + i]; }
    sh[t] = s;
    __syncthreads();
    for (int o = 1; o < 1024; o <<= 1) {
        int v = (t >= o) ? sh[t - o] : 0;
        __syncthreads();
        sh[t] += v;
        __syncthreads();
    }
    int off = (t == 0) ? 0 : sh[t - 1];
#pragma unroll
    for (int i = 0; i < 32; i++) rowptr[base + i] = off + local[i];
    if (t == 1023) rowptr[NN] = sh[1023];
}

__global__ void fill5_kernel(const int* __restrict__ sidx, const int* __restrict__ eidx,
                             const float* __restrict__ sattr,
                             const int* __restrict__ rowptr_all, int* __restrict__ cnt_all,
                             int2* __restrict__ cedge_all, int* __restrict__ csrc4) {
    int g = blockIdx.y;
    int e = blockIdx.x * blockDim.x + threadIdx.x;
    if (e >= ESZ) return;
    const int* rowptr = rowptr_all + (size_t)g * (NN + 1);
    int* cursor = cnt_all + (size_t)g * 2 * NN + NN;
    if (g < 4) {
        const int* src = sidx + (size_t)g * 2 * ESZ;
        const int* dst = src + ESZ;
        const float* attr = sattr + (size_t)g * ESZ;
        int d = dst[e];
        int pos = rowptr[d] + atomicAdd(&cursor[d], 1);
        cedge_all[(size_t)g * ESZ + pos] = make_int2(src[e], __float_as_int(attr[e]));
    } else {
        int d = eidx[EGZ + e];
        int pos = rowptr[d] + atomicAdd(&cursor[d], 1);
        csrc4[pos] = eidx[e];
    }
}

// ---------------- CSR gathers (warp per node) ----------------
__global__ void gatherA_kernel(const int* __restrict__ rowptr_all, const int2* __restrict__ cedge_all,
                               const float* __restrict__ in,
                               float* __restrict__ xs0, float* __restrict__ xh_base) {
    int g = blockIdx.y;
    const int* rowptr = rowptr_all + (size_t)g * (NN + 1);
    const int2* ce = cedge_all + (size_t)g * ESZ;
    int warp = (blockIdx.x * blockDim.x + threadIdx.x) >> 5;
    int lane = threadIdx.x & 31;
    if (warp >= NN) return;
    int beg = rowptr[warp], end = rowptr[warp + 1];
    float a0 = 0.f, a1 = 0.f;
    for (int e = beg; e < end; e++) {
        int2 p = ce[e];
        float a = __int_as_float(p.y);
        const float* ip = in + (size_t)p.x * FF;
        a0 += a * ip[lane];
        a1 += a * ip[32 + lane];
    }
    float* out = (g == 0) ? xs0 : (xh_base + (size_t)(g - 1) * NN * FF);
    if (g > 0) { a0 = fabsf(a0); a1 = fabsf(a1); }
    float* op = out + (size_t)warp * FF;
    op[lane] = a0;
    op[32 + lane] = a1;
}

__global__ void gather3_kernel(const int* __restrict__ rowptr, const int2* __restrict__ ce,
                               const float* __restrict__ in0, const float* __restrict__ in1,
                               const float* __restrict__ in2,
                               float* __restrict__ o0, float* __restrict__ o1,
                               float* __restrict__ o2) {
    int warp = (blockIdx.x * blockDim.x + threadIdx.x) >> 5;
    int lane = threadIdx.x & 31;
    if (warp >= NN) return;
    int beg = rowptr[warp], end = rowptr[warp + 1];
    float a00 = 0.f, a01 = 0.f, a10 = 0.f, a11 = 0.f, a20 = 0.f, a21 = 0.f;
    for (int e = beg; e < end; e++) {
        int2 p = ce[e];
        float a = __int_as_float(p.y);
        size_t r = (size_t)p.x * FF;
        a00 += a * in0[r + lane];  a01 += a * in0[r + 32 + lane];
        a10 += a * in1[r + lane];  a11 += a * in1[r + 32 + lane];
        a20 += a * in2[r + lane];  a21 += a * in2[r + 32 + lane];
    }
    size_t w = (size_t)warp * FF;
    o0[w + lane] = a00;  o0[w + 32 + lane] = a01;
    o1[w + lane] = a10;  o1[w + 32 + lane] = a11;
    o2[w + lane] = a20;  o2[w + 32 + lane] = a21;
}

// ---------------- GEMM 1 (tensor core 3xTF32): h = xs@W, fused a_s/a_d ----------
// BM=64, BN=64 (one head), K=64 in one smem pass. 256 threads = 8 warps (4x2).
// grid.x = (NN/64)*4heads, grid.z = layer.
// dyn smem: AHI[64][68], ALO, BHI[64][68] (n-major), BLO = 4*4352 floats = 69632 B
#define SMW 68
#define T1_AHI 0
#define T1_ALO 4352
#define T1_BHI 8704
#define T1_BLO 13056

__global__ void __launch_bounds__(256) gemm1_tc(
        const float* __restrict__ xs_all, const float* __restrict__ W_all,
        float* __restrict__ h_all,
        const float* __restrict__ asrc_all, const float* __restrict__ adst_all,
        float* __restrict__ as_all, float* __restrict__ ad_all) {
    extern __shared__ float sm[];
    float* AHI = sm + T1_AHI;
    float* ALO = sm + T1_ALO;
    float* BHI = sm + T1_BHI;
    float* BLO = sm + T1_BLO;
    int layer = blockIdx.z;
    int head = blockIdx.x & 3;
    int bm = (blockIdx.x >> 2) * 64;
    const float* A = xs_all + (size_t)layer * NN * FF;
    const float* B = W_all + (size_t)layer * FF * HF + head * 64;
    float* Ch = h_all + (size_t)layer * NN * HF;

    int tid = threadIdx.x;
    int lane = tid & 31, warp = tid >> 5;
    int wr = warp >> 1, wc = warp & 1;
    int g = lane >> 2, t4 = lane & 3;

    // load + split A tile [64 rows][64 k]
    {
        int row = tid >> 2;
        int cb = (tid & 3) * 4;
#pragma unroll
        for (int i = 0; i < 4; i++) {
            int c = cb + i * 16;
            float4 v = *(const float4*)(A + (size_t)(bm + row) * FF + c);
            float hx, hy, hz, hw;
            hx = __uint_as_float(f2tf32(v.x)); hy = __uint_as_float(f2tf32(v.y));
            hz = __uint_as_float(f2tf32(v.z)); hw = __uint_as_float(f2tf32(v.w));
            AHI[row * SMW + c + 0] = hx; ALO[row * SMW + c + 0] = __uint_as_float(f2tf32(v.x - hx));
            AHI[row * SMW + c + 1] = hy; ALO[row * SMW + c + 1] = __uint_as_float(f2tf32(v.y - hy));
            AHI[row * SMW + c + 2] = hz; ALO[row * SMW + c + 2] = __uint_as_float(f2tf32(v.z - hz));
            AHI[row * SMW + c + 3] = hw; ALO[row * SMW + c + 3] = __uint_as_float(f2tf32(v.w - hw));
        }
    }
    // load + split + transpose B tile: Bs[n][k]
    {
        int kb = tid >> 4;          // 0..15
        int n4 = (tid & 15) * 4;
#pragma unroll
        for (int i = 0; i < 4; i++) {
            int k = kb + i * 16;
            float4 v = *(const float4*)(B + (size_t)k * HF + n4);
            float vv[4] = {v.x, v.y, v.z, v.w};
#pragma unroll
            for (int e = 0; e < 4; e++) {
                float hi = __uint_as_float(f2tf32(vv[e]));
                BHI[(n4 + e) * SMW + k] = hi;
                BLO[(n4 + e) * SMW + k] = __uint_as_float(f2tf32(vv[e] - hi));
            }
        }
    }
    __syncthreads();

    int m0 = wr * 16, n0 = wc * 32;
    float c[4][4] = {};
#pragma unroll
    for (int ks = 0; ks < 8; ks++) {
        int k0 = ks * 8;
        uint32_t ah[4], al[4];
        ah[0] = __float_as_uint(AHI[(m0 + g) * SMW + k0 + t4]);
        ah[1] = __float_as_uint(AHI[(m0 + g + 8) * SMW + k0 + t4]);
        ah[2] = __float_as_uint(AHI[(m0 + g) * SMW + k0 + t4 + 4]);
        ah[3] = __float_as_uint(AHI[(m0 + g + 8) * SMW + k0 + t4 + 4]);
        al[0] = __float_as_uint(ALO[(m0 + g) * SMW + k0 + t4]);
        al[1] = __float_as_uint(ALO[(m0 + g + 8) * SMW + k0 + t4]);
        al[2] = __float_as_uint(ALO[(m0 + g) * SMW + k0 + t4 + 4]);
        al[3] = __float_as_uint(ALO[(m0 + g + 8) * SMW + k0 + t4 + 4]);
#pragma unroll
        for (int j = 0; j < 4; j++) {
            int n = n0 + 8 * j + g;
            uint32_t bh[2], bl[2];
            bh[0] = __float_as_uint(BHI[n * SMW + k0 + t4]);
            bh[1] = __float_as_uint(BHI[n * SMW + k0 + t4 + 4]);
            bl[0] = __float_as_uint(BLO[n * SMW + k0 + t4]);
            bl[1] = __float_as_uint(BLO[n * SMW + k0 + t4 + 4]);
            mma_tf32(c[j], al, bh);
            mma_tf32(c[j], ah, bl);
            mma_tf32(c[j], ah, bh);
        }
    }

    // store h + prepare asad partials
    const float* asrc = asrc_all + (size_t)layer * HH * FF + head * 64;
    const float* adst = adst_all + (size_t)layer * HH * FF + head * 64;
    float ps1 = 0.f, ps2 = 0.f, pd1 = 0.f, pd2 = 0.f;
#pragma unroll
    for (int j = 0; j < 4; j++) {
        int colL = n0 + 8 * j + 2 * t4;     // within head [0,64)
        int r1 = bm + m0 + g, r2 = r1 + 8;
        *(float2*)(Ch + (size_t)r1 * HF + head * 64 + colL) = make_float2(c[j][0], c[j][1]);
        *(float2*)(Ch + (size_t)r2 * HF + head * 64 + colL) = make_float2(c[j][2], c[j][3]);
        float w0s = asrc[colL], w1s = asrc[colL + 1];
        float w0d = adst[colL], w1d = adst[colL + 1];
        ps1 += c[j][0] * w0s + c[j][1] * w1s;
        ps2 += c[j][2] * w0s + c[j][3] * w1s;
        pd1 += c[j][0] * w0d + c[j][1] * w1d;
        pd2 += c[j][2] * w0d + c[j][3] * w1d;
    }
    // reduce over t4 (lanes differing in bits 0..1)
#pragma unroll
    for (int o = 1; o < 4; o <<= 1) {
        ps1 += __shfl_xor_sync(0xffffffffu, ps1, o);
        ps2 += __shfl_xor_sync(0xffffffffu, ps2, o);
        pd1 += __shfl_xor_sync(0xffffffffu, pd1, o);
        pd2 += __shfl_xor_sync(0xffffffffu, pd2, o);
    }
    __syncthreads();           // done reading smem tiles; reuse for reduction
    float* shS = sm;           // [64][2]
    float* shD = sm + 128;     // [64][2]
    if (t4 == 0) {
        int rb1 = m0 + g, rb2 = rb1 + 8;
        shS[rb1 * 2 + wc] = ps1;  shS[rb2 * 2 + wc] = ps2;
        shD[rb1 * 2 + wc] = pd1;  shD[rb2 * 2 + wc] = pd2;
    }
    __syncthreads();
    if (tid < 64) {
        float s = shS[tid * 2] + shS[tid * 2 + 1];
        float dd = shD[tid * 2] + shD[tid * 2 + 1];
        as_all[(size_t)layer * NN * HH + (size_t)(bm + tid) * 4 + head] = s;
        ad_all[(size_t)layer * NN * HH + (size_t)(bm + tid) * 4 + head] = dd;
    }
}

// ---------------- GEMM 2 (tensor core 3xTF32): z = gacc@W + b, BN partials ----
// BM=64, Nc=64, K=256 in 4 chunks of 64. grid.x = NN/64, grid.z = layer.
__global__ void __launch_bounds__(256) gemm2_tc(
        const float* __restrict__ gacc_all, const float* __restrict__ W_all,
        const float* __restrict__ bias_all, float* __restrict__ z_all,
        float* __restrict__ part) {
    extern __shared__ float sm[];
    float* AHI = sm + T1_AHI;
    float* ALO = sm + T1_ALO;
    float* BHI = sm + T1_BHI;
    float* BLO = sm + T1_BLO;
    int layer = blockIdx.z;
    int bm = blockIdx.x * 64;
    const float* A = gacc_all + (size_t)layer * NN * HF;
    const float* B = W_all + (size_t)layer * HF * FF;
    const float* bias = bias_all + (size_t)layer * FF;
    float* Cz = z_all + (size_t)layer * NN * FF;

    int tid = threadIdx.x;
    int lane = tid & 31, warp = tid >> 5;
    int wr = warp >> 1, wc = warp & 1;
    int g = lane >> 2, t4 = lane & 3;
    int m0 = wr * 16, n0 = wc * 32;
    float c[4][4] = {};

    for (int kc = 0; kc < 4; kc++) {
        int kg = kc * 64;
        __syncthreads();
        {
            int row = tid >> 2;
            int cb = (tid & 3) * 4;
#pragma unroll
            for (int i = 0; i < 4; i++) {
                int cc = cb + i * 16;
                float4 v = *(const float4*)(A + (size_t)(bm + row) * HF + kg + cc);
                float hx = __uint_as_float(f2tf32(v.x));
                float hy = __uint_as_float(f2tf32(v.y));
                float hz = __uint_as_float(f2tf32(v.z));
                float hw = __uint_as_float(f2tf32(v.w));
                AHI[row * SMW + cc + 0] = hx; ALO[row * SMW + cc + 0] = __uint_as_float(f2tf32(v.x - hx));
                AHI[row * SMW + cc + 1] = hy; ALO[row * SMW + cc + 1] = __uint_as_float(f2tf32(v.y - hy));
                AHI[row * SMW + cc + 2] = hz; ALO[row * SMW + cc + 2] = __uint_as_float(f2tf32(v.z - hz));
                AHI[row * SMW + cc + 3] = hw; ALO[row * SMW + cc + 3] = __uint_as_float(f2tf32(v.w - hw));
            }
        }
        {
            int kb = tid >> 4;
            int n4 = (tid & 15) * 4;
#pragma unroll
            for (int i = 0; i < 4; i++) {
                int k = kb + i * 16;
                float4 v = *(const float4*)(B + (size_t)(kg + k) * FF + n4);
                float vv[4] = {v.x, v.y, v.z, v.w};
#pragma unroll
                for (int e = 0; e < 4; e++) {
                    float hi = __uint_as_float(f2tf32(vv[e]));
                    BHI[(n4 + e) * SMW + k] = hi;
                    BLO[(n4 + e) * SMW + k] = __uint_as_float(f2tf32(vv[e] - hi));
                }
            }
        }
        __syncthreads();
#pragma unroll
        for (int ks = 0; ks < 8; ks++) {
            int k0 = ks * 8;
            uint32_t ah[4], al[4];
            ah[0] = __float_as_uint(AHI[(m0 + g) * SMW + k0 + t4]);
            ah[1] = __float_as_uint(AHI[(m0 + g + 8) * SMW + k0 + t4]);
            ah[2] = __float_as_uint(AHI[(m0 + g) * SMW + k0 + t4 + 4]);
            ah[3] = __float_as_uint(AHI[(m0 + g + 8) * SMW + k0 + t4 + 4]);
            al[0] = __float_as_uint(ALO[(m0 + g) * SMW + k0 + t4]);
            al[1] = __float_as_uint(ALO[(m0 + g + 8) * SMW + k0 + t4]);
            al[2] = __float_as_uint(ALO[(m0 + g) * SMW + k0 + t4 + 4]);
            al[3] = __float_as_uint(ALO[(m0 + g + 8) * SMW + k0 + t4 + 4]);
#pragma unroll
            for (int j = 0; j < 4; j++) {
                int n = n0 + 8 * j + g;
                uint32_t bh[2], bl[2];
                bh[0] = __float_as_uint(BHI[n * SMW + k0 + t4]);
                bh[1] = __float_as_uint(BHI[n * SMW + k0 + t4 + 4]);
                bl[0] = __float_as_uint(BLO[n * SMW + k0 + t4]);
                bl[1] = __float_as_uint(BLO[n * SMW + k0 + t4 + 4]);
                mma_tf32(c[j], al, bh);
                mma_tf32(c[j], ah, bl);
                mma_tf32(c[j], ah, bh);
            }
        }
    }

    // epilogue: bias, store z, per-column sums/sumsq
    float csum[4][2], csq[4][2];
#pragma unroll
    for (int j = 0; j < 4; j++) {
        int col = n0 + 8 * j + 2 * t4;
        float b0 = bias[col], b1 = bias[col + 1];
        float v00 = c[j][0] + b0, v01 = c[j][1] + b1;
        float v10 = c[j][2] + b0, v11 = c[j][3] + b1;
        int r1 = bm + m0 + g, r2 = r1 + 8;
        *(float2*)(Cz + (size_t)r1 * FF + col) = make_float2(v00, v01);
        *(float2*)(Cz + (size_t)r2 * FF + col) = make_float2(v10, v11);
        csum[j][0] = v00 + v10;  csq[j][0] = v00 * v00 + v10 * v10;
        csum[j][1] = v01 + v11;  csq[j][1] = v01 * v01 + v11 * v11;
    }
    // reduce over g (lanes differing in bits 2..4)
#pragma unroll
    for (int o = 4; o < 32; o <<= 1) {
#pragma unroll
        for (int j = 0; j < 4; j++) {
            csum[j][0] += __shfl_xor_sync(0xffffffffu, csum[j][0], o);
            csum[j][1] += __shfl_xor_sync(0xffffffffu, csum[j][1], o);
            csq[j][0]  += __shfl_xor_sync(0xffffffffu, csq[j][0], o);
            csq[j][1]  += __shfl_xor_sync(0xffffffffu, csq[j][1], o);
        }
    }
    __syncthreads();
    float* shsum = sm;         // [64][4]
    float* shsq  = sm + 256;   // [64][4]
    if (g == 0) {
#pragma unroll
        for (int j = 0; j < 4; j++) {
            int col = n0 + 8 * j + 2 * t4;
            shsum[col * 4 + wr] = csum[j][0];  shsq[col * 4 + wr] = csq[j][0];
            shsum[(col + 1) * 4 + wr] = csum[j][1];  shsq[(col + 1) * 4 + wr] = csq[j][1];
        }
    }
    __syncthreads();
    if (tid < 64) {
        float s = shsum[tid * 4] + shsum[tid * 4 + 1] + shsum[tid * 4 + 2] + shsum[tid * 4 + 3];
        float q = shsq[tid * 4] + shsq[tid * 4 + 1] + shsq[tid * 4 + 2] + shsq[tid * 4 + 3];
        size_t pi = ((size_t)layer * 512 + blockIdx.x) * 64 + tid;
        part[pi * 2 + 0] = s;
        part[pi * 2 + 1] = q;
    }
}

// reduce 512 block partials per layer -> mu, rstd. grid.x = layer.
__global__ void bnstat2_kernel(const float* __restrict__ part,
                               float* __restrict__ mu_all, float* __restrict__ rstd_all) {
    int layer = blockIdx.x;
    int t = threadIdx.x;
    int c = t & 63;
    int cg = t >> 6;            // 4 chunks of 128 blocks
    double s = 0.0, q = 0.0;
    for (int b = cg * 128; b < (cg + 1) * 128; b++) {
        size_t pi = ((size_t)layer * 512 + b) * 64 + c;
        s += part[pi * 2 + 0];
        q += part[pi * 2 + 1];
    }
    __shared__ double shs[256], shq[256];
    shs[t] = s; shq[t] = q;
    __syncthreads();
    if (cg == 0) {
        s = shs[c] + shs[64 + c] + shs[128 + c] + shs[192 + c];
        q = shq[c] + shq[64 + c] + shq[128 + c] + shq[192 + c];
        double mu = s / NN;
        double var = q / NN - mu * mu;
        mu_all[(size_t)layer * FF + c] = (float)mu;
        rstd_all[(size_t)layer * FF + c] = rsqrtf((float)var + BNEPS);
    }
}

// ---------------- GAT aggregation (warp per node, one layer) ----------------
__global__ void gat_agg_kernel(const int* __restrict__ rowptr, const int* __restrict__ csrc,
                               const float* __restrict__ a_s, const float* __restrict__ a_d,
                               const float* __restrict__ h, const float* __restrict__ gb,
                               float* __restrict__ outx) {
    int warp = (blockIdx.x * blockDim.x + threadIdx.x) >> 5;
    int lane = threadIdx.x & 31;
    if (warp >= NN) return;
    int d = warp;
    int beg = rowptr[d], end = rowptr[d + 1];
    float4 ad4 = *(const float4*)(a_d + (size_t)d * 4);
    float4 sf4 = *(const float4*)(a_s + (size_t)d * 4);
    float sl0 = lrelu(sf4.x + ad4.x);
    float sl1 = lrelu(sf4.y + ad4.y);
    float sl2 = lrelu(sf4.z + ad4.z);
    float sl3 = lrelu(sf4.w + ad4.w);
    float m0 = sl0, m1 = sl1, m2 = sl2, m3 = sl3;
    for (int e = beg + lane; e < end; e += 32) {
        int s = csrc[e];
        float4 s4 = *(const float4*)(a_s + (size_t)s * 4);
        m0 = fmaxf(m0, lrelu(s4.x + ad4.x));
        m1 = fmaxf(m1, lrelu(s4.y + ad4.y));
        m2 = fmaxf(m2, lrelu(s4.z + ad4.z));
        m3 = fmaxf(m3, lrelu(s4.w + ad4.w));
    }
    for (int o = 16; o; o >>= 1) {
        m0 = fmaxf(m0, __shfl_xor_sync(0xffffffffu, m0, o));
        m1 = fmaxf(m1, __shfl_xor_sync(0xffffffffu, m1, o));
        m2 = fmaxf(m2, __shfl_xor_sync(0xffffffffu, m2, o));
        m3 = fmaxf(m3, __shfl_xor_sync(0xffffffffu, m3, o));
    }
    float acc[8];
    float den0, den1, den2, den3;
    {
        float e0 = expf(sl0 - m0), e1 = expf(sl1 - m1);
        float e2 = expf(sl2 - m2), e3 = expf(sl3 - m3);
        den0 = e0; den1 = e1; den2 = e2; den3 = e3;
        const float* hp = h + (size_t)d * HF;
        acc[0] = e0 * hp[lane];        acc[1] = e0 * hp[32 + lane];
        acc[2] = e1 * hp[64 + lane];   acc[3] = e1 * hp[96 + lane];
        acc[4] = e2 * hp[128 + lane];  acc[5] = e2 * hp[160 + lane];
        acc[6] = e3 * hp[192 + lane];  acc[7] = e3 * hp[224 + lane];
    }
    for (int c0 = beg; c0 < end; c0 += 32) {
        int e = c0 + lane;
        int sl = 0;
        float x0 = 0.f, x1 = 0.f, x2 = 0.f, x3 = 0.f;
        if (e < end) {
            sl = csrc[e];
            float4 s4 = *(const float4*)(a_s + (size_t)sl * 4);
            x0 = expf(lrelu(s4.x + ad4.x) - m0);
            x1 = expf(lrelu(s4.y + ad4.y) - m1);
            x2 = expf(lrelu(s4.z + ad4.z) - m2);
            x3 = expf(lrelu(s4.w + ad4.w) - m3);
        }
        int cnt = min(32, end - c0);
        for (int i = 0; i < cnt; i++) {
            int s   = __shfl_sync(0xffffffffu, sl, i);
            float e0 = __shfl_sync(0xffffffffu, x0, i);
            float e1 = __shfl_sync(0xffffffffu, x1, i);
            float e2 = __shfl_sync(0xffffffffu, x2, i);
            float e3 = __shfl_sync(0xffffffffu, x3, i);
            den0 += e0; den1 += e1; den2 += e2; den3 += e3;
            const float* hp = h + (size_t)s * HF;
            acc[0] += e0 * hp[lane];        acc[1] += e0 * hp[32 + lane];
            acc[2] += e1 * hp[64 + lane];   acc[3] += e1 * hp[96 + lane];
            acc[4] += e2 * hp[128 + lane];  acc[5] += e2 * hp[160 + lane];
            acc[6] += e3 * hp[192 + lane];  acc[7] += e3 * hp[224 + lane];
        }
    }
    float den[4] = {den0, den1, den2, den3};
    float* op = outx + (size_t)d * HF;
#pragma unroll
    for (int j = 0; j < 8; j++) {
        int c = j * 32 + lane;
        op[c] = elu(acc[j] / den[j >> 1] + gb[c]);
    }
}

// ---------------- fused BN apply + residual + pool ----------------
__global__ void bnpool_kernel(const float* __restrict__ x, const float* __restrict__ z_all,
                              const float* __restrict__ g_all, const float* __restrict__ beta_all,
                              const float* __restrict__ mu_all, const float* __restrict__ rstd_all,
                              const int* __restrict__ batch, float* __restrict__ pooled) {
    int idx = blockIdx.x * blockDim.x + threadIdx.x;
    if (idx >= NN * FF) return;
    int n = idx >> 6, f = idx & 63;
    float v = x[idx];
#pragma unroll
    for (int i = 0; i < 4; i++) {
        float zz = z_all[(size_t)i * NN * FF + idx];
        v += (zz - mu_all[i * FF + f]) * rstd_all[i * FF + f] * g_all[i * FF + f]
             + beta_all[i * FF + f];
    }
    atomicAdd(&pooled[batch[n] * FF + f], v);
}

// ---------------- tiny FC + BN head ----------------
__global__ void fcbn_kernel(const float* __restrict__ A, const float* __restrict__ W,
                            const float* __restrict__ b, const float* __restrict__ g,
                            const float* __restrict__ beta, float* __restrict__ out,
                            int K, int Nc, int do_relu) {
    int j = blockIdx.x;
    int r = threadIdx.x;
    float y = b[j];
    for (int k = 0; k < K; k++) y += A[r * K + k] * W[k * Nc + j];
    __shared__ float sh[GG];
    __shared__ float s_mu, s_var;
    sh[r] = y;
    __syncthreads();
    if (r == 0) {
        float s = 0.f;
        for (int i = 0; i < GG; i++) s += sh[i];
        float mu = s / GG;
        float q = 0.f;
        for (int i = 0; i < GG; i++) { float dd = sh[i] - mu; q += dd * dd; }
        s_mu = mu; s_var = q / GG;
    }
    __syncthreads();
    float o = (y - s_mu) * rsqrtf(s_var + BNEPS) * g[j] + beta[j];
    if (do_relu) o = fmaxf(o, 0.f);
    out[r * Nc + j] = o;
}

// ---------------- launch ----------------
static inline void* sym(const void* s) {
    void* p = nullptr;
    cudaGetSymbolAddress(&p, s);
    return p;
}

extern "C" void kernel_launch(void* const* d_in, const int* in_sizes, int n_in,
                              void* d_out, int out_size) {
    const float* x       = (const float*)d_in[0];
    const int*  eidx     = (const int*)d_in[1];
    const int*  batch    = (const int*)d_in[2];
    const int*  sidx     = (const int*)d_in[3];
    const float* sattr   = (const float*)d_in[4];
    const float* gat_W   = (const float*)d_in[5];
    const float* gat_as  = (const float*)d_in[6];
    const float* gat_ad  = (const float*)d_in[7];
    const float* gat_b   = (const float*)d_in[8];
    const float* mlp_W   = (const float*)d_in[9];
    const float* mlp_b   = (const float*)d_in[10];
    const float* mlp_g   = (const float*)d_in[11];
    const float* mlp_be  = (const float*)d_in[12];
    const float* fc1_W   = (const float*)d_in[13];
    const float* fc1_b   = (const float*)d_in[14];
    const float* fc1_g   = (const float*)d_in[15];
    const float* fc1_be  = (const float*)d_in[16];
    const float* fc2_W   = (const float*)d_in[17];
    const float* fc2_b   = (const float*)d_in[18];
    const float* fc2_g   = (const float*)d_in[19];
    const float* fc2_be  = (const float*)d_in[20];
    const float* fc3_W   = (const float*)d_in[21];
    const float* fc3_b   = (const float*)d_in[22];
    const float* fc3_g   = (const float*)d_in[23];
    const float* fc3_be  = (const float*)d_in[24];
    float* out = (float*)d_out;

    float* p_xs     = (float*)sym(d_xs);
    float* p_xh     = (float*)sym(d_xh);
    float* p_h      = (float*)sym(d_h);
    float* p_as     = (float*)sym(d_as);
    float* p_ad     = (float*)sym(d_ad);
    float* p_gacc   = (float*)sym(d_gacc);
    float* p_z      = (float*)sym(d_z);
    float* p_bnpart = (float*)sym(d_bnpart);
    float* p_bnmu   = (float*)sym(d_bnmu);
    float* p_bnrstd = (float*)sym(d_bnrstd);
    float* p_pooled = (float*)sym(d_pooled);
    float* p_h1     = (float*)sym(d_h1);
    float* p_h2     = (float*)sym(d_h2);
    int*   p_cnt    = (int*)sym(d_cnt);
    int*   p_rowptr = (int*)sym(d_rowptr);
    int2*  p_cedge  = (int2*)sym(d_cedge);
    int*   p_csrc4  = (int*)sym(d_csrc4);

    const int TB = 256;
    const int EB = (ESZ + TB - 1) / TB;
    const int NW = (NN * 32 + TB - 1) / TB;
    const int SMEM_TC = 4 * 4352 * 4;   // 69632 B

    static int smem_set = 0;
    cudaFuncSetAttribute(gemm1_tc, cudaFuncAttributeMaxDynamicSharedMemorySize, SMEM_TC);
    cudaFuncSetAttribute(gemm2_tc, cudaFuncAttributeMaxDynamicSharedMemorySize, SMEM_TC);
    (void)smem_set;

    // ---- batched CSR build (5 graphs) ----
    zero_i_kernel<<<(10 * NN + TB - 1) / TB, TB>>>(p_cnt, 10 * NN);
    hist5_kernel<<<dim3(EB, 5), TB>>>(sidx, eidx, p_cnt);
    scan5_kernel<<<5, 1024>>>(p_cnt, p_rowptr);
    fill5_kernel<<<dim3(EB, 5), TB>>>(sidx, eidx, sattr, p_rowptr, p_cnt, p_cedge, p_csrc4);

    // ---- solo passes (gather form) ----
    gatherA_kernel<<<dim3(NW, 4), TB>>>(p_rowptr, p_cedge, x, p_xs, p_xh);
    gather3_kernel<<<NW, TB>>>(p_rowptr, p_cedge,
                               p_xh, p_xh + (size_t)NN * FF, p_xh + (size_t)2 * NN * FF,
                               p_xs + (size_t)NN * FF, p_xs + (size_t)2 * NN * FF,
                               p_xs + (size_t)3 * NN * FF);

    // ---- batched tensor-core GEMM1 + fused a_s/a_d (all 4 layers) ----
    gemm1_tc<<<dim3((NN / 64) * 4, 1, 4), TB, SMEM_TC>>>(p_xs, gat_W, p_h, gat_as, gat_ad,
                                                         p_as, p_ad);

    // ---- GAT aggregation per layer (keeps each h_i L2-resident) ----
    const int* gat_rp = p_rowptr + (size_t)4 * (NN + 1);
    for (int i = 0; i < 4; i++) {
        gat_agg_kernel<<<NW, TB>>>(gat_rp, p_csrc4,
                                   p_as + (size_t)i * NN * HH, p_ad + (size_t)i * NN * HH,
                                   p_h + (size_t)i * NN * HF, gat_b + (size_t)i * HF,
                                   p_gacc + (size_t)i * NN * HF);
    }

    // ---- batched tensor-core GEMM2 + fused BN partials ----
    gemm2_tc<<<dim3(NN / 64, 1, 4), TB, SMEM_TC>>>(p_gacc, mlp_W, mlp_b, p_z, p_bnpart);
    bnstat2_kernel<<<4, 256>>>(p_bnpart, p_bnmu, p_bnrstd);

    // ---- fused BN apply + residual + pool ----
    zero_f_kernel<<<(GG * FF / 4 + TB - 1) / TB, TB>>>((float4*)p_pooled, GG * FF / 4);
    bnpool_kernel<<<(NN * FF + TB - 1) / TB, TB>>>(x, p_z, mlp_g, mlp_be, p_bnmu, p_bnrstd,
                                                   batch, p_pooled);

    // ---- FC head ----
    fcbn_kernel<<<256, GG>>>(p_pooled, fc1_W, fc1_b, fc1_g, fc1_be, p_h1, 64, 256, 1);
    fcbn_kernel<<<128, GG>>>(p_h1, fc2_W, fc2_b, fc2_g, fc2_be, p_h2, 256, 128, 1);
    fcbn_kernel<<<NCLS, GG>>>(p_h2, fc3_W, fc3_b, fc3_g, fc3_be, out, 128, NCLS, 0);
}

// round 10
// speedup vs baseline: 1.1671x; 1.1671x over previous
#include <cuda_runtime.h>
#include <cuda_fp16.h>
#include <math.h>

#define NN   32768
#define FF   64
#define HH   4
#define HF   256
#define ESZ  524288
#define EGZ  524288
#define GG   64
#define NCLS 10
#define BNEPS 1e-5f

// ---------------- device scratch (static allocation only) ----------------
__device__ float   d_xs[4][NN*FF];      // x0..x3 (GAT inputs)
__device__ float   d_xh[3][NN*FF];      // xh1..xh3 intermediates
__device__ __half2 d_h[4][NN*HF/2];     // h_i = xs_i @ W_i  (fp16 storage)
__device__ float   d_as[4][NN*HH];
__device__ float   d_ad[4][NN*HH];
__device__ float   d_gacc[4][NN*HF];    // elu(gat output) per layer
__device__ float   d_z[4][NN*FF];       // mlp output per layer
__device__ float   d_bnpart[4*256*FF*2];
__device__ float   d_bnmu[4][FF];
__device__ float   d_bnrstd[4][FF];
__device__ float   d_pooled[GG*FF];
__device__ float   d_h1[GG*256];
__device__ float   d_h2[GG*128];
// CSR scratch: graphs 0..3 = scatter graphs (packed src+attr), 4 = gat edges
__device__ int     d_cnt[5][2*NN];
__device__ int     d_rowptr[5][NN+1];
__device__ int2    d_cedge[4][ESZ];
__device__ int     d_csrc4[ESZ];

// ---------------- helpers ----------------
__device__ __forceinline__ float lrelu(float x) { return x >= 0.f ? x : 0.2f * x; }
__device__ __forceinline__ float elu(float x)   { return x > 0.f ? x : expm1f(x); }

__global__ void zero_i_kernel(int* p, int n) {
    int i = blockIdx.x * blockDim.x + threadIdx.x;
    if (i < n) p[i] = 0;
}
__global__ void zero_f_kernel(float4* p, int n4) {
    int i = blockIdx.x * blockDim.x + threadIdx.x;
    if (i < n4) p[i] = make_float4(0.f, 0.f, 0.f, 0.f);
}

// ---------------- batched CSR build (5 graphs at once) ----------------
__global__ void hist5_kernel(const int* __restrict__ sidx, const int* __restrict__ eidx,
                             int* __restrict__ cnt) {
    int g = blockIdx.y;
    const int* dst = (g < 4) ? (sidx + (size_t)g * 2 * ESZ + ESZ) : (eidx + EGZ);
    int e = blockIdx.x * blockDim.x + threadIdx.x;
    if (e < ESZ) atomicAdd(&cnt[(size_t)g * 2 * NN + dst[e]], 1);
}

__global__ void scan5_kernel(const int* __restrict__ cnt_all, int* __restrict__ rowptr_all) {
    int g = blockIdx.x;
    const int* cnt = cnt_all + (size_t)g * 2 * NN;
    int* rowptr = rowptr_all + (size_t)g * (NN + 1);
    __shared__ int sh[1024];
    int t = threadIdx.x;
    int base = t * 32;
    int local[32];
    int s = 0;
#pragma unroll
    for (int i = 0; i < 32; i++) { local[i] = s; s += cnt[base + i]; }
    sh[t] = s;
    __syncthreads();
    for (int o = 1; o < 1024; o <<= 1) {
        int v = (t >= o) ? sh[t - o] : 0;
        __syncthreads();
        sh[t] += v;
        __syncthreads();
    }
    int off = (t == 0) ? 0 : sh[t - 1];
#pragma unroll
    for (int i = 0; i < 32; i++) rowptr[base + i] = off + local[i];
    if (t == 1023) rowptr[NN] = sh[1023];
}

__global__ void fill5_kernel(const int* __restrict__ sidx, const int* __restrict__ eidx,
                             const float* __restrict__ sattr,
                             const int* __restrict__ rowptr_all, int* __restrict__ cnt_all,
                             int2* __restrict__ cedge_all, int* __restrict__ csrc4) {
    int g = blockIdx.y;
    int e = blockIdx.x * blockDim.x + threadIdx.x;
    if (e >= ESZ) return;
    const int* rowptr = rowptr_all + (size_t)g * (NN + 1);
    int* cursor = cnt_all + (size_t)g * 2 * NN + NN;
    if (g < 4) {
        const int* src = sidx + (size_t)g * 2 * ESZ;
        const int* dst = src + ESZ;
        const float* attr = sattr + (size_t)g * ESZ;
        int d = dst[e];
        int pos = rowptr[d] + atomicAdd(&cursor[d], 1);
        cedge_all[(size_t)g * ESZ + pos] = make_int2(src[e], __float_as_int(attr[e]));
    } else {
        int d = eidx[EGZ + e];
        int pos = rowptr[d] + atomicAdd(&cursor[d], 1);
        csrc4[pos] = eidx[e];
    }
}

// ---------------- CSR gathers (warp per node) ----------------
__global__ void gatherA_kernel(const int* __restrict__ rowptr_all, const int2* __restrict__ cedge_all,
                               const float* __restrict__ in,
                               float* __restrict__ xs0, float* __restrict__ xh_base) {
    int g = blockIdx.y;
    const int* rowptr = rowptr_all + (size_t)g * (NN + 1);
    const int2* ce = cedge_all + (size_t)g * ESZ;
    int warp = (blockIdx.x * blockDim.x + threadIdx.x) >> 5;
    int lane = threadIdx.x & 31;
    if (warp >= NN) return;
    int beg = rowptr[warp], end = rowptr[warp + 1];
    float a0 = 0.f, a1 = 0.f;
    for (int e = beg; e < end; e++) {
        int2 p = ce[e];
        float a = __int_as_float(p.y);
        const float* ip = in + (size_t)p.x * FF;
        a0 += a * ip[lane];
        a1 += a * ip[32 + lane];
    }
    float* out = (g == 0) ? xs0 : (xh_base + (size_t)(g - 1) * NN * FF);
    if (g > 0) { a0 = fabsf(a0); a1 = fabsf(a1); }
    float* op = out + (size_t)warp * FF;
    op[lane] = a0;
    op[32 + lane] = a1;
}

__global__ void gather3_kernel(const int* __restrict__ rowptr, const int2* __restrict__ ce,
                               const float* __restrict__ in0, const float* __restrict__ in1,
                               const float* __restrict__ in2,
                               float* __restrict__ o0, float* __restrict__ o1,
                               float* __restrict__ o2) {
    int warp = (blockIdx.x * blockDim.x + threadIdx.x) >> 5;
    int lane = threadIdx.x & 31;
    if (warp >= NN) return;
    int beg = rowptr[warp], end = rowptr[warp + 1];
    float a00 = 0.f, a01 = 0.f, a10 = 0.f, a11 = 0.f, a20 = 0.f, a21 = 0.f;
    for (int e = beg; e < end; e++) {
        int2 p = ce[e];
        float a = __int_as_float(p.y);
        size_t r = (size_t)p.x * FF;
        a00 += a * in0[r + lane];  a01 += a * in0[r + 32 + lane];
        a10 += a * in1[r + lane];  a11 += a * in1[r + 32 + lane];
        a20 += a * in2[r + lane];  a21 += a * in2[r + 32 + lane];
    }
    size_t w = (size_t)warp * FF;
    o0[w + lane] = a00;  o0[w + 32 + lane] = a01;
    o1[w + lane] = a10;  o1[w + 32 + lane] = a11;
    o2[w + lane] = a20;  o2[w + 32 + lane] = a21;
}

// ---------------- GEMM 1 (batched over layers): h = xs@W, fused a_s/a_d ----------
// BM=128, BN=64(one head), BK=16, 256 threads, 8x4 per thread. h stored as half2.
// grid.x = (NN/128)*4heads, grid.z = layer.
__global__ void gemm_asad_kernel(const float* __restrict__ xs_all, const float* __restrict__ W_all,
                                 __half2* __restrict__ h_all,
                                 const float* __restrict__ asrc_all, const float* __restrict__ adst_all,
                                 float* __restrict__ as_all, float* __restrict__ ad_all) {
    const int K = FF, Nc = HF;
    int layer = blockIdx.z;
    const float* A = xs_all + (size_t)layer * NN * FF;
    const float* B = W_all + (size_t)layer * FF * HF;
    __half2* Ch = h_all + (size_t)layer * NN * (HF / 2);
    const float* asrc = asrc_all + (size_t)layer * HH * FF;
    const float* adst = adst_all + (size_t)layer * HH * FF;
    float* a_s = as_all + (size_t)layer * NN * HH;
    float* a_d = ad_all + (size_t)layer * NN * HH;

    __shared__ float As[16][132];
    __shared__ float Bs[16][68];
    __shared__ float shs[128][17];
    __shared__ float shd[128][17];
    int tid = threadIdx.x;
    int tx = tid & 15, ty = tid >> 4;
    int hh = blockIdx.x & 3;
    int bm = (blockIdx.x >> 2) * 128;
    int bn = hh * 64;
    float acc[8][4] = {};
    for (int k0 = 0; k0 < K; k0 += 16) {
        {
            int kk = (tid & 3) * 4;
#pragma unroll
            for (int p = 0; p < 2; p++) {
                int m = (tid >> 2) + p * 64;
                float4 v = *(const float4*)(A + (size_t)(bm + m) * K + k0 + kk);
                As[kk + 0][m] = v.x; As[kk + 1][m] = v.y; As[kk + 2][m] = v.z; As[kk + 3][m] = v.w;
            }
        }
        {
            int kk = tid >> 4;
            int n = (tid & 15) * 4;
            *(float4*)&Bs[kk][n] = *(const float4*)(B + (size_t)(k0 + kk) * Nc + bn + n);
        }
        __syncthreads();
#pragma unroll
        for (int kk = 0; kk < 16; kk++) {
            float4 a0 = *(float4*)&As[kk][ty * 8];
            float4 a1 = *(float4*)&As[kk][ty * 8 + 4];
            float4 b  = *(float4*)&Bs[kk][tx * 4];
            float ar[8] = {a0.x, a0.y, a0.z, a0.w, a1.x, a1.y, a1.z, a1.w};
#pragma unroll
            for (int i = 0; i < 8; i++) {
                acc[i][0] += ar[i] * b.x;
                acc[i][1] += ar[i] * b.y;
                acc[i][2] += ar[i] * b.z;
                acc[i][3] += ar[i] * b.w;
            }
        }
        __syncthreads();
    }
    // store h as half2 (two half2 = 8B per row)
#pragma unroll
    for (int i = 0; i < 8; i++) {
        __half2 p01 = __floats2half2_rn(acc[i][0], acc[i][1]);
        __half2 p23 = __floats2half2_rn(acc[i][2], acc[i][3]);
        __half2 pk[2] = {p01, p23};
        *(float2*)(Ch + (size_t)(bm + ty * 8 + i) * (HF / 2) + (bn + tx * 4) / 2) =
            *(float2*)pk;
    }
    // fused head-dot (from fp32 accumulators)
    float ws[4], wd[4];
#pragma unroll
    for (int j = 0; j < 4; j++) {
        ws[j] = asrc[hh * 64 + tx * 4 + j];
        wd[j] = adst[hh * 64 + tx * 4 + j];
    }
#pragma unroll
    for (int i = 0; i < 8; i++) {
        float ps = acc[i][0] * ws[0] + acc[i][1] * ws[1] + acc[i][2] * ws[2] + acc[i][3] * ws[3];
        float pd = acc[i][0] * wd[0] + acc[i][1] * wd[1] + acc[i][2] * wd[2] + acc[i][3] * wd[3];
        shs[ty * 8 + i][tx] = ps;
        shd[ty * 8 + i][tx] = pd;
    }
    __syncthreads();
    if (tid < 128) {
        float s = 0.f, dd = 0.f;
#pragma unroll
        for (int t = 0; t < 16; t++) { s += shs[tid][t]; dd += shd[tid][t]; }
        a_s[(size_t)(bm + tid) * 4 + hh] = s;
        a_d[(size_t)(bm + tid) * 4 + hh] = dd;
    }
}

// ---------------- GEMM 2 (batched): z = gacc@W + b, fused BN partials ----------
// BM=128, Nc=64, K=256. grid.x = NN/128, grid.z = layer.
__global__ void gemm_bn_kernel(const float* __restrict__ gacc_all, const float* __restrict__ W_all,
                               const float* __restrict__ bias_all, float* __restrict__ z_all,
                               float* __restrict__ part) {
    const int K = HF, Nc = FF;
    int layer = blockIdx.z;
    const float* A = gacc_all + (size_t)layer * NN * HF;
    const float* B = W_all + (size_t)layer * HF * FF;
    const float* bias = bias_all + (size_t)layer * FF;
    float* C = z_all + (size_t)layer * NN * FF;

    __shared__ float As[16][132];
    __shared__ float Bs[16][68];
    __shared__ float shs[64][17];
    __shared__ float shq[64][17];
    int tid = threadIdx.x;
    int tx = tid & 15, ty = tid >> 4;
    int bm = blockIdx.x * 128;
    float acc[8][4] = {};
    for (int k0 = 0; k0 < K; k0 += 16) {
        {
            int kk = (tid & 3) * 4;
#pragma unroll
            for (int p = 0; p < 2; p++) {
                int m = (tid >> 2) + p * 64;
                float4 v = *(const float4*)(A + (size_t)(bm + m) * K + k0 + kk);
                As[kk + 0][m] = v.x; As[kk + 1][m] = v.y; As[kk + 2][m] = v.z; As[kk + 3][m] = v.w;
            }
        }
        {
            int kk = tid >> 4;
            int n = (tid & 15) * 4;
            *(float4*)&Bs[kk][n] = *(const float4*)(B + (size_t)(k0 + kk) * Nc + n);
        }
        __syncthreads();
#pragma unroll
        for (int kk = 0; kk < 16; kk++) {
            float4 a0 = *(float4*)&As[kk][ty * 8];
            float4 a1 = *(float4*)&As[kk][ty * 8 + 4];
            float4 b  = *(float4*)&Bs[kk][tx * 4];
            float ar[8] = {a0.x, a0.y, a0.z, a0.w, a1.x, a1.y, a1.z, a1.w};
#pragma unroll
            for (int i = 0; i < 8; i++) {
                acc[i][0] += ar[i] * b.x;
                acc[i][1] += ar[i] * b.y;
                acc[i][2] += ar[i] * b.z;
                acc[i][3] += ar[i] * b.w;
            }
        }
        __syncthreads();
    }
    float bs[4];
#pragma unroll
    for (int j = 0; j < 4; j++) bs[j] = bias[tx * 4 + j];
    float colsum[4] = {}, colsq[4] = {};
#pragma unroll
    for (int i = 0; i < 8; i++) {
        float v0 = acc[i][0] + bs[0];
        float v1 = acc[i][1] + bs[1];
        float v2 = acc[i][2] + bs[2];
        float v3 = acc[i][3] + bs[3];
        *(float4*)(C + (size_t)(bm + ty * 8 + i) * Nc + tx * 4) = make_float4(v0, v1, v2, v3);
        colsum[0] += v0; colsq[0] += v0 * v0;
        colsum[1] += v1; colsq[1] += v1 * v1;
        colsum[2] += v2; colsq[2] += v2 * v2;
        colsum[3] += v3; colsq[3] += v3 * v3;
    }
#pragma unroll
    for (int j = 0; j < 4; j++) {
        shs[tx * 4 + j][ty] = colsum[j];
        shq[tx * 4 + j][ty] = colsq[j];
    }
    __syncthreads();
    if (tid < 64) {
        float s = 0.f, q = 0.f;
#pragma unroll
        for (int t = 0; t < 16; t++) { s += shs[tid][t]; q += shq[tid][t]; }
        size_t pi = ((size_t)layer * 256 + blockIdx.x) * 64 + tid;
        part[pi * 2 + 0] = s;
        part[pi * 2 + 1] = q;
    }
}

// reduce 256 block partials per layer -> mu, rstd. grid.x = layer.
__global__ void bnstat2_kernel(const float* __restrict__ part,
                               float* __restrict__ mu_all, float* __restrict__ rstd_all) {
    int layer = blockIdx.x;
    int t = threadIdx.x;
    int c = t & 63;
    int cg = t >> 6;            // 4 chunks of 64 blocks
    double s = 0.0, q = 0.0;
    for (int b = cg * 64; b < (cg + 1) * 64; b++) {
        size_t pi = ((size_t)layer * 256 + b) * 64 + c;
        s += part[pi * 2 + 0];
        q += part[pi * 2 + 1];
    }
    __shared__ double shs[256], shq[256];
    shs[t] = s; shq[t] = q;
    __syncthreads();
    if (cg == 0) {
        s = shs[c] + shs[64 + c] + shs[128 + c] + shs[192 + c];
        q = shq[c] + shq[64 + c] + shq[128 + c] + shq[192 + c];
        double mu = s / NN;
        double var = q / NN - mu * mu;
        mu_all[(size_t)layer * FF + c] = (float)mu;
        rstd_all[(size_t)layer * FF + c] = rsqrtf((float)var + BNEPS);
    }
}

// ---------------- GAT aggregation (warp per node, one layer, half2 h) ----------
__global__ void gat_agg_kernel(const int* __restrict__ rowptr, const int* __restrict__ csrc,
                               const float* __restrict__ a_s, const float* __restrict__ a_d,
                               const __half2* __restrict__ h, const float* __restrict__ gb,
                               float* __restrict__ outx) {
    int warp = (blockIdx.x * blockDim.x + threadIdx.x) >> 5;
    int lane = threadIdx.x & 31;
    if (warp >= NN) return;
    int d = warp;
    int beg = rowptr[d], end = rowptr[d + 1];
    float4 ad4 = *(const float4*)(a_d + (size_t)d * 4);
    float4 sf4 = *(const float4*)(a_s + (size_t)d * 4);
    float sl0 = lrelu(sf4.x + ad4.x);
    float sl1 = lrelu(sf4.y + ad4.y);
    float sl2 = lrelu(sf4.z + ad4.z);
    float sl3 = lrelu(sf4.w + ad4.w);
    float m0 = sl0, m1 = sl1, m2 = sl2, m3 = sl3;
    for (int e = beg + lane; e < end; e += 32) {
        int s = csrc[e];
        float4 s4 = *(const float4*)(a_s + (size_t)s * 4);
        m0 = fmaxf(m0, lrelu(s4.x + ad4.x));
        m1 = fmaxf(m1, lrelu(s4.y + ad4.y));
        m2 = fmaxf(m2, lrelu(s4.z + ad4.z));
        m3 = fmaxf(m3, lrelu(s4.w + ad4.w));
    }
    for (int o = 16; o; o >>= 1) {
        m0 = fmaxf(m0, __shfl_xor_sync(0xffffffffu, m0, o));
        m1 = fmaxf(m1, __shfl_xor_sync(0xffffffffu, m1, o));
        m2 = fmaxf(m2, __shfl_xor_sync(0xffffffffu, m2, o));
        m3 = fmaxf(m3, __shfl_xor_sync(0xffffffffu, m3, o));
    }
    // accumulators: per j (=head), lane covers half2 index j*32+lane = cols {2i, 2i+1}
    float ax[4], ay[4];
    float den0, den1, den2, den3;
    {
        float e0 = expf(sl0 - m0), e1 = expf(sl1 - m1);
        float e2 = expf(sl2 - m2), e3 = expf(sl3 - m3);
        den0 = e0; den1 = e1; den2 = e2; den3 = e3;
        float ee[4] = {e0, e1, e2, e3};
        const __half2* hp = h + (size_t)d * (HF / 2);
#pragma unroll
        for (int j = 0; j < 4; j++) {
            float2 f = __half22float2(hp[j * 32 + lane]);
            ax[j] = ee[j] * f.x;
            ay[j] = ee[j] * f.y;
        }
    }
    for (int c0 = beg; c0 < end; c0 += 32) {
        int e = c0 + lane;
        int sl = 0;
        float x0 = 0.f, x1 = 0.f, x2 = 0.f, x3 = 0.f;
        if (e < end) {
            sl = csrc[e];
            float4 s4 = *(const float4*)(a_s + (size_t)sl * 4);
            x0 = expf(lrelu(s4.x + ad4.x) - m0);
            x1 = expf(lrelu(s4.y + ad4.y) - m1);
            x2 = expf(lrelu(s4.z + ad4.z) - m2);
            x3 = expf(lrelu(s4.w + ad4.w) - m3);
        }
        int cnt = min(32, end - c0);
        for (int i = 0; i < cnt; i++) {
            int s   = __shfl_sync(0xffffffffu, sl, i);
            float e0 = __shfl_sync(0xffffffffu, x0, i);
            float e1 = __shfl_sync(0xffffffffu, x1, i);
            float e2 = __shfl_sync(0xffffffffu, x2, i);
            float e3 = __shfl_sync(0xffffffffu, x3, i);
            den0 += e0; den1 += e1; den2 += e2; den3 += e3;
            float ee[4] = {e0, e1, e2, e3};
            const __half2* hp = h + (size_t)s * (HF / 2);
#pragma unroll
            for (int j = 0; j < 4; j++) {
                float2 f = __half22float2(hp[j * 32 + lane]);
                ax[j] += ee[j] * f.x;
                ay[j] += ee[j] * f.y;
            }
        }
    }
    float den[4] = {den0, den1, den2, den3};
    float* op = outx + (size_t)d * HF;
#pragma unroll
    for (int j = 0; j < 4; j++) {
        int c0 = 2 * (j * 32 + lane);
        float inv = 1.f / den[j];
        float ox = elu(ax[j] * inv + gb[c0]);
        float oy = elu(ay[j] * inv + gb[c0 + 1]);
        *(float2*)(op + c0) = make_float2(ox, oy);
    }
}

// ---------------- fused BN apply + residual + pool ----------------
__global__ void bnpool_kernel(const float* __restrict__ x, const float* __restrict__ z_all,
                              const float* __restrict__ g_all, const float* __restrict__ beta_all,
                              const float* __restrict__ mu_all, const float* __restrict__ rstd_all,
                              const int* __restrict__ batch, float* __restrict__ pooled) {
    int idx = blockIdx.x * blockDim.x + threadIdx.x;
    if (idx >= NN * FF) return;
    int n = idx >> 6, f = idx & 63;
    float v = x[idx];
#pragma unroll
    for (int i = 0; i < 4; i++) {
        float zz = z_all[(size_t)i * NN * FF + idx];
        v += (zz - mu_all[i * FF + f]) * rstd_all[i * FF + f] * g_all[i * FF + f]
             + beta_all[i * FF + f];
    }
    atomicAdd(&pooled[batch[n] * FF + f], v);
}

// ---------------- tiny FC + BN head ----------------
__global__ void fcbn_kernel(const float* __restrict__ A, const float* __restrict__ W,
                            const float* __restrict__ b, const float* __restrict__ g,
                            const float* __restrict__ beta, float* __restrict__ out,
                            int K, int Nc, int do_relu) {
    int j = blockIdx.x;
    int r = threadIdx.x;
    float y = b[j];
    for (int k = 0; k < K; k++) y += A[r * K + k] * W[k * Nc + j];
    __shared__ float sh[GG];
    __shared__ float s_mu, s_var;
    sh[r] = y;
    __syncthreads();
    if (r == 0) {
        float s = 0.f;
        for (int i = 0; i < GG; i++) s += sh[i];
        float mu = s / GG;
        float q = 0.f;
        for (int i = 0; i < GG; i++) { float dd = sh[i] - mu; q += dd * dd; }
        s_mu = mu; s_var = q / GG;
    }
    __syncthreads();
    float o = (y - s_mu) * rsqrtf(s_var + BNEPS) * g[j] + beta[j];
    if (do_relu) o = fmaxf(o, 0.f);
    out[r * Nc + j] = o;
}

// ---------------- launch ----------------
static inline void* sym(const void* s) {
    void* p = nullptr;
    cudaGetSymbolAddress(&p, s);
    return p;
}

extern "C" void kernel_launch(void* const* d_in, const int* in_sizes, int n_in,
                              void* d_out, int out_size) {
    const float* x       = (const float*)d_in[0];
    const int*  eidx     = (const int*)d_in[1];
    const int*  batch    = (const int*)d_in[2];
    const int*  sidx     = (const int*)d_in[3];
    const float* sattr   = (const float*)d_in[4];
    const float* gat_W   = (const float*)d_in[5];
    const float* gat_as  = (const float*)d_in[6];
    const float* gat_ad  = (const float*)d_in[7];
    const float* gat_b   = (const float*)d_in[8];
    const float* mlp_W   = (const float*)d_in[9];
    const float* mlp_b   = (const float*)d_in[10];
    const float* mlp_g   = (const float*)d_in[11];
    const float* mlp_be  = (const float*)d_in[12];
    const float* fc1_W   = (const float*)d_in[13];
    const float* fc1_b   = (const float*)d_in[14];
    const float* fc1_g   = (const float*)d_in[15];
    const float* fc1_be  = (const float*)d_in[16];
    const float* fc2_W   = (const float*)d_in[17];
    const float* fc2_b   = (const float*)d_in[18];
    const float* fc2_g   = (const float*)d_in[19];
    const float* fc2_be  = (const float*)d_in[20];
    const float* fc3_W   = (const float*)d_in[21];
    const float* fc3_b   = (const float*)d_in[22];
    const float* fc3_g   = (const float*)d_in[23];
    const float* fc3_be  = (const float*)d_in[24];
    float* out = (float*)d_out;

    float*   p_xs     = (float*)sym(d_xs);
    float*   p_xh     = (float*)sym(d_xh);
    __half2* p_h      = (__half2*)sym(d_h);
    float*   p_as     = (float*)sym(d_as);
    float*   p_ad     = (float*)sym(d_ad);
    float*   p_gacc   = (float*)sym(d_gacc);
    float*   p_z      = (float*)sym(d_z);
    float*   p_bnpart = (float*)sym(d_bnpart);
    float*   p_bnmu   = (float*)sym(d_bnmu);
    float*   p_bnrstd = (float*)sym(d_bnrstd);
    float*   p_pooled = (float*)sym(d_pooled);
    float*   p_h1     = (float*)sym(d_h1);
    float*   p_h2     = (float*)sym(d_h2);
    int*     p_cnt    = (int*)sym(d_cnt);
    int*     p_rowptr = (int*)sym(d_rowptr);
    int2*    p_cedge  = (int2*)sym(d_cedge);
    int*     p_csrc4  = (int*)sym(d_csrc4);

    const int TB = 256;
    const int EB = (ESZ + TB - 1) / TB;
    const int NW = (NN * 32 + TB - 1) / TB;

    // ---- batched CSR build (5 graphs) ----
    zero_i_kernel<<<(10 * NN + TB - 1) / TB, TB>>>(p_cnt, 10 * NN);
    hist5_kernel<<<dim3(EB, 5), TB>>>(sidx, eidx, p_cnt);
    scan5_kernel<<<5, 1024>>>(p_cnt, p_rowptr);
    fill5_kernel<<<dim3(EB, 5), TB>>>(sidx, eidx, sattr, p_rowptr, p_cnt, p_cedge, p_csrc4);

    // ---- solo passes (gather form) ----
    gatherA_kernel<<<dim3(NW, 4), TB>>>(p_rowptr, p_cedge, x, p_xs, p_xh);
    gather3_kernel<<<NW, TB>>>(p_rowptr, p_cedge,
                               p_xh, p_xh + (size_t)NN * FF, p_xh + (size_t)2 * NN * FF,
                               p_xs + (size_t)NN * FF, p_xs + (size_t)2 * NN * FF,
                               p_xs + (size_t)3 * NN * FF);

    // ---- batched GEMM1 + fused a_s/a_d (all 4 layers) ----
    gemm_asad_kernel<<<dim3((NN / 128) * 4, 1, 4), TB>>>(p_xs, gat_W, p_h, gat_as, gat_ad,
                                                         p_as, p_ad);

    // ---- GAT aggregation per layer (keeps each h_i L2-resident) ----
    const int* gat_rp = p_rowptr + (size_t)4 * (NN + 1);
    for (int i = 0; i < 4; i++) {
        gat_agg_kernel<<<NW, TB>>>(gat_rp, p_csrc4,
                                   p_as + (size_t)i * NN * HH, p_ad + (size_t)i * NN * HH,
                                   p_h + (size_t)i * NN * (HF / 2), gat_b + (size_t)i * HF,
                                   p_gacc + (size_t)i * NN * HF);
    }

    // ---- batched GEMM2 + fused BN partials ----
    gemm_bn_kernel<<<dim3(NN / 128, 1, 4), TB>>>(p_gacc, mlp_W, mlp_b, p_z, p_bnpart);
    bnstat2_kernel<<<4, 256>>>(p_bnpart, p_bnmu, p_bnrstd);

    // ---- fused BN apply + residual + pool ----
    zero_f_kernel<<<(GG * FF / 4 + TB - 1) / TB, TB>>>((float4*)p_pooled, GG * FF / 4);
    bnpool_kernel<<<(NN * FF + TB - 1) / TB, TB>>>(x, p_z, mlp_g, mlp_be, p_bnmu, p_bnrstd,
                                                   batch, p_pooled);

    // ---- FC head ----
    fcbn_kernel<<<256, GG>>>(p_pooled, fc1_W, fc1_b, fc1_g, fc1_be, p_h1, 64, 256, 1);
    fcbn_kernel<<<128, GG>>>(p_h1, fc2_W, fc2_b, fc2_g, fc2_be, p_h2, 256, 128, 1);
    fcbn_kernel<<<NCLS, GG>>>(p_h2, fc3_W, fc3_b, fc3_g, fc3_be, out, 128, NCLS, 0);
}

// round 13
// speedup vs baseline: 1.3525x; 1.1588x over previous
#include <cuda_runtime.h>
#include <cuda_fp16.h>
#include <math.h>

#define NN   32768
#define FF   64
#define HH   4
#define HF   256
#define ESZ  524288
#define EGZ  524288
#define GG   64
#define NCLS 10
#define BNEPS 1e-5f

// ---------------- device scratch (static allocation only) ----------------
__device__ float   d_xs[4][NN*FF];      // x0..x3 (GAT inputs)
__device__ float   d_xh[3][NN*FF];      // xh1..xh3 intermediates
__device__ __half2 d_h[4][NN*HF/2];     // h_i = xs_i @ W_i  (fp16 storage)
__device__ float   d_as[4][NN*HH];
__device__ float   d_ad[4][NN*HH];
__device__ float   d_gacc[4][NN*HF];    // elu(gat output) per layer
__device__ float   d_z[4][NN*FF];       // mlp output per layer
__device__ float   d_bnpart[4*256*FF*2];
__device__ float   d_bnmu[4][FF];
__device__ float   d_bnrstd[4][FF];
__device__ float   d_pooled[GG*FF];
__device__ float   d_h1[GG*256];
__device__ float   d_h2[GG*128];
// CSR scratch: graphs 0..3 = scatter graphs (packed src+attr), 4 = gat edges
__device__ int     d_cnt[5][2*NN];
__device__ int     d_rowptr[5][NN+1];
__device__ int2    d_cedge[4][ESZ];
__device__ int     d_csrc4[ESZ];

// ---------------- helpers ----------------
__device__ __forceinline__ float lrelu(float x) { return x >= 0.f ? x : 0.2f * x; }
__device__ __forceinline__ float elu(float x)   { return x > 0.f ? x : expm1f(x); }

__global__ void zero_i_kernel(int* p, int n) {
    int i = blockIdx.x * blockDim.x + threadIdx.x;
    if (i < n) p[i] = 0;
}
__global__ void zero_f_kernel(float4* p, int n4) {
    int i = blockIdx.x * blockDim.x + threadIdx.x;
    if (i < n4) p[i] = make_float4(0.f, 0.f, 0.f, 0.f);
}

// ---------------- batched CSR build (5 graphs at once) ----------------
__global__ void hist5_kernel(const int* __restrict__ sidx, const int* __restrict__ eidx,
                             int* __restrict__ cnt) {
    int g = blockIdx.y;
    const int* dst = (g < 4) ? (sidx + (size_t)g * 2 * ESZ + ESZ) : (eidx + EGZ);
    int e = blockIdx.x * blockDim.x + threadIdx.x;
    if (e < ESZ) atomicAdd(&cnt[(size_t)g * 2 * NN + dst[e]], 1);
}

__global__ void scan5_kernel(const int* __restrict__ cnt_all, int* __restrict__ rowptr_all) {
    int g = blockIdx.x;
    const int* cnt = cnt_all + (size_t)g * 2 * NN;
    int* rowptr = rowptr_all + (size_t)g * (NN + 1);
    __shared__ int sh[1024];
    int t = threadIdx.x;
    int base = t * 32;
    int local[32];
    int s = 0;
#pragma unroll
    for (int i = 0; i < 32; i++) { local[i] = s; s += cnt[base + i]; }
    sh[t] = s;
    __syncthreads();
    for (int o = 1; o < 1024; o <<= 1) {
        int v = (t >= o) ? sh[t - o] : 0;
        __syncthreads();
        sh[t] += v;
        __syncthreads();
    }
    int off = (t == 0) ? 0 : sh[t - 1];
#pragma unroll
    for (int i = 0; i < 32; i++) rowptr[base + i] = off + local[i];
    if (t == 1023) rowptr[NN] = sh[1023];
}

__global__ void fill5_kernel(const int* __restrict__ sidx, const int* __restrict__ eidx,
                             const float* __restrict__ sattr,
                             const int* __restrict__ rowptr_all, int* __restrict__ cnt_all,
                             int2* __restrict__ cedge_all, int* __restrict__ csrc4) {
    int g = blockIdx.y;
    int e = blockIdx.x * blockDim.x + threadIdx.x;
    if (e >= ESZ) return;
    const int* rowptr = rowptr_all + (size_t)g * (NN + 1);
    int* cursor = cnt_all + (size_t)g * 2 * NN + NN;
    if (g < 4) {
        const int* src = sidx + (size_t)g * 2 * ESZ;
        const int* dst = src + ESZ;
        const float* attr = sattr + (size_t)g * ESZ;
        int d = dst[e];
        int pos = rowptr[d] + atomicAdd(&cursor[d], 1);
        cedge_all[(size_t)g * ESZ + pos] = make_int2(src[e], __float_as_int(attr[e]));
    } else {
        int d = eidx[EGZ + e];
        int pos = rowptr[d] + atomicAdd(&cursor[d], 1);
        csrc4[pos] = eidx[e];
    }
}

// ---------------- CSR gathers (warp per node) ----------------
__global__ void gatherA_kernel(const int* __restrict__ rowptr_all, const int2* __restrict__ cedge_all,
                               const float* __restrict__ in,
                               float* __restrict__ xs0, float* __restrict__ xh_base) {
    int g = blockIdx.y;
    const int* rowptr = rowptr_all + (size_t)g * (NN + 1);
    const int2* ce = cedge_all + (size_t)g * ESZ;
    int warp = (blockIdx.x * blockDim.x + threadIdx.x) >> 5;
    int lane = threadIdx.x & 31;
    if (warp >= NN) return;
    int beg = rowptr[warp], end = rowptr[warp + 1];
    float a0 = 0.f, a1 = 0.f;
    for (int e = beg; e < end; e++) {
        int2 p = ce[e];
        float a = __int_as_float(p.y);
        const float* ip = in + (size_t)p.x * FF;
        a0 += a * ip[lane];
        a1 += a * ip[32 + lane];
    }
    float* out = (g == 0) ? xs0 : (xh_base + (size_t)(g - 1) * NN * FF);
    if (g > 0) { a0 = fabsf(a0); a1 = fabsf(a1); }
    float* op = out + (size_t)warp * FF;
    op[lane] = a0;
    op[32 + lane] = a1;
}

__global__ void gather3_kernel(const int* __restrict__ rowptr, const int2* __restrict__ ce,
                               const float* __restrict__ in0, const float* __restrict__ in1,
                               const float* __restrict__ in2,
                               float* __restrict__ o0, float* __restrict__ o1,
                               float* __restrict__ o2) {
    int warp = (blockIdx.x * blockDim.x + threadIdx.x) >> 5;
    int lane = threadIdx.x & 31;
    if (warp >= NN) return;
    int beg = rowptr[warp], end = rowptr[warp + 1];
    float a00 = 0.f, a01 = 0.f, a10 = 0.f, a11 = 0.f, a20 = 0.f, a21 = 0.f;
    for (int e = beg; e < end; e++) {
        int2 p = ce[e];
        float a = __int_as_float(p.y);
        size_t r = (size_t)p.x * FF;
        a00 += a * in0[r + lane];  a01 += a * in0[r + 32 + lane];
        a10 += a * in1[r + lane];  a11 += a * in1[r + 32 + lane];
        a20 += a * in2[r + lane];  a21 += a * in2[r + 32 + lane];
    }
    size_t w = (size_t)warp * FF;
    o0[w + lane] = a00;  o0[w + 32 + lane] = a01;
    o1[w + lane] = a10;  o1[w + 32 + lane] = a11;
    o2[w + lane] = a20;  o2[w + 32 + lane] = a21;
}

// ---------------- GEMM 1 (batched over layers): h = xs@W, fused a_s/a_d ----------
__global__ void gemm_asad_kernel(const float* __restrict__ xs_all, const float* __restrict__ W_all,
                                 __half2* __restrict__ h_all,
                                 const float* __restrict__ asrc_all, const float* __restrict__ adst_all,
                                 float* __restrict__ as_all, float* __restrict__ ad_all) {
    const int K = FF, Nc = HF;
    int layer = blockIdx.z;
    const float* A = xs_all + (size_t)layer * NN * FF;
    const float* B = W_all + (size_t)layer * FF * HF;
    __half2* Ch = h_all + (size_t)layer * NN * (HF / 2);
    const float* asrc = asrc_all + (size_t)layer * HH * FF;
    const float* adst = adst_all + (size_t)layer * HH * FF;
    float* a_s = as_all + (size_t)layer * NN * HH;
    float* a_d = ad_all + (size_t)layer * NN * HH;

    __shared__ float As[16][132];
    __shared__ float Bs[16][68];
    __shared__ float shs[128][17];
    __shared__ float shd[128][17];
    int tid = threadIdx.x;
    int tx = tid & 15, ty = tid >> 4;
    int hh = blockIdx.x & 3;
    int bm = (blockIdx.x >> 2) * 128;
    int bn = hh * 64;
    float acc[8][4] = {};
    for (int k0 = 0; k0 < K; k0 += 16) {
        {
            int kk = (tid & 3) * 4;
#pragma unroll
            for (int p = 0; p < 2; p++) {
                int m = (tid >> 2) + p * 64;
                float4 v = *(const float4*)(A + (size_t)(bm + m) * K + k0 + kk);
                As[kk + 0][m] = v.x; As[kk + 1][m] = v.y; As[kk + 2][m] = v.z; As[kk + 3][m] = v.w;
            }
        }
        {
            int kk = tid >> 4;
            int n = (tid & 15) * 4;
            *(float4*)&Bs[kk][n] = *(const float4*)(B + (size_t)(k0 + kk) * Nc + bn + n);
        }
        __syncthreads();
#pragma unroll
        for (int kk = 0; kk < 16; kk++) {
            float4 a0 = *(float4*)&As[kk][ty * 8];
            float4 a1 = *(float4*)&As[kk][ty * 8 + 4];
            float4 b  = *(float4*)&Bs[kk][tx * 4];
            float ar[8] = {a0.x, a0.y, a0.z, a0.w, a1.x, a1.y, a1.z, a1.w};
#pragma unroll
            for (int i = 0; i < 8; i++) {
                acc[i][0] += ar[i] * b.x;
                acc[i][1] += ar[i] * b.y;
                acc[i][2] += ar[i] * b.z;
                acc[i][3] += ar[i] * b.w;
            }
        }
        __syncthreads();
    }
#pragma unroll
    for (int i = 0; i < 8; i++) {
        __half2 p01 = __floats2half2_rn(acc[i][0], acc[i][1]);
        __half2 p23 = __floats2half2_rn(acc[i][2], acc[i][3]);
        __half2 pk[2] = {p01, p23};
        *(float2*)(Ch + (size_t)(bm + ty * 8 + i) * (HF / 2) + (bn + tx * 4) / 2) =
            *(float2*)pk;
    }
    float ws[4], wd[4];
#pragma unroll
    for (int j = 0; j < 4; j++) {
        ws[j] = asrc[hh * 64 + tx * 4 + j];
        wd[j] = adst[hh * 64 + tx * 4 + j];
    }
#pragma unroll
    for (int i = 0; i < 8; i++) {
        float ps = acc[i][0] * ws[0] + acc[i][1] * ws[1] + acc[i][2] * ws[2] + acc[i][3] * ws[3];
        float pd = acc[i][0] * wd[0] + acc[i][1] * wd[1] + acc[i][2] * wd[2] + acc[i][3] * wd[3];
        shs[ty * 8 + i][tx] = ps;
        shd[ty * 8 + i][tx] = pd;
    }
    __syncthreads();
    if (tid < 128) {
        float s = 0.f, dd = 0.f;
#pragma unroll
        for (int t = 0; t < 16; t++) { s += shs[tid][t]; dd += shd[tid][t]; }
        a_s[(size_t)(bm + tid) * 4 + hh] = s;
        a_d[(size_t)(bm + tid) * 4 + hh] = dd;
    }
}

// ---------------- GEMM 2 (batched): z = gacc@W + b, fused BN partials ----------
__global__ void gemm_bn_kernel(const float* __restrict__ gacc_all, const float* __restrict__ W_all,
                               const float* __restrict__ bias_all, float* __restrict__ z_all,
                               float* __restrict__ part) {
    const int K = HF, Nc = FF;
    int layer = blockIdx.z;
    const float* A = gacc_all + (size_t)layer * NN * HF;
    const float* B = W_all + (size_t)layer * HF * FF;
    const float* bias = bias_all + (size_t)layer * FF;
    float* C = z_all + (size_t)layer * NN * FF;

    __shared__ float As[16][132];
    __shared__ float Bs[16][68];
    __shared__ float shs[64][17];
    __shared__ float shq[64][17];
    int tid = threadIdx.x;
    int tx = tid & 15, ty = tid >> 4;
    int bm = blockIdx.x * 128;
    float acc[8][4] = {};
    for (int k0 = 0; k0 < K; k0 += 16) {
        {
            int kk = (tid & 3) * 4;
#pragma unroll
            for (int p = 0; p < 2; p++) {
                int m = (tid >> 2) + p * 64;
                float4 v = *(const float4*)(A + (size_t)(bm + m) * K + k0 + kk);
                As[kk + 0][m] = v.x; As[kk + 1][m] = v.y; As[kk + 2][m] = v.z; As[kk + 3][m] = v.w;
            }
        }
        {
            int kk = tid >> 4;
            int n = (tid & 15) * 4;
            *(float4*)&Bs[kk][n] = *(const float4*)(B + (size_t)(k0 + kk) * Nc + n);
        }
        __syncthreads();
#pragma unroll
        for (int kk = 0; kk < 16; kk++) {
            float4 a0 = *(float4*)&As[kk][ty * 8];
            float4 a1 = *(float4*)&As[kk][ty * 8 + 4];
            float4 b  = *(float4*)&Bs[kk][tx * 4];
            float ar[8] = {a0.x, a0.y, a0.z, a0.w, a1.x, a1.y, a1.z, a1.w};
#pragma unroll
            for (int i = 0; i < 8; i++) {
                acc[i][0] += ar[i] * b.x;
                acc[i][1] += ar[i] * b.y;
                acc[i][2] += ar[i] * b.z;
                acc[i][3] += ar[i] * b.w;
            }
        }
        __syncthreads();
    }
    float bs[4];
#pragma unroll
    for (int j = 0; j < 4; j++) bs[j] = bias[tx * 4 + j];
    float colsum[4] = {}, colsq[4] = {};
#pragma unroll
    for (int i = 0; i < 8; i++) {
        float v0 = acc[i][0] + bs[0];
        float v1 = acc[i][1] + bs[1];
        float v2 = acc[i][2] + bs[2];
        float v3 = acc[i][3] + bs[3];
        *(float4*)(C + (size_t)(bm + ty * 8 + i) * Nc + tx * 4) = make_float4(v0, v1, v2, v3);
        colsum[0] += v0; colsq[0] += v0 * v0;
        colsum[1] += v1; colsq[1] += v1 * v1;
        colsum[2] += v2; colsq[2] += v2 * v2;
        colsum[3] += v3; colsq[3] += v3 * v3;
    }
#pragma unroll
    for (int j = 0; j < 4; j++) {
        shs[tx * 4 + j][ty] = colsum[j];
        shq[tx * 4 + j][ty] = colsq[j];
    }
    __syncthreads();
    if (tid < 64) {
        float s = 0.f, q = 0.f;
#pragma unroll
        for (int t = 0; t < 16; t++) { s += shs[tid][t]; q += shq[tid][t]; }
        size_t pi = ((size_t)layer * 256 + blockIdx.x) * 64 + tid;
        part[pi * 2 + 0] = s;
        part[pi * 2 + 1] = q;
    }
}

// reduce 256 block partials per layer -> mu, rstd. grid.x = layer.
__global__ void bnstat2_kernel(const float* __restrict__ part,
                               float* __restrict__ mu_all, float* __restrict__ rstd_all) {
    int layer = blockIdx.x;
    int t = threadIdx.x;
    int c = t & 63;
    int cg = t >> 6;
    double s = 0.0, q = 0.0;
    for (int b = cg * 64; b < (cg + 1) * 64; b++) {
        size_t pi = ((size_t)layer * 256 + b) * 64 + c;
        s += part[pi * 2 + 0];
        q += part[pi * 2 + 1];
    }
    __shared__ double shs[256], shq[256];
    shs[t] = s; shq[t] = q;
    __syncthreads();
    if (cg == 0) {
        s = shs[c] + shs[64 + c] + shs[128 + c] + shs[192 + c];
        q = shq[c] + shq[64 + c] + shq[128 + c] + shq[192 + c];
        double mu = s / NN;
        double var = q / NN - mu * mu;
        mu_all[(size_t)layer * FF + c] = (float)mu;
        rstd_all[(size_t)layer * FF + c] = rsqrtf((float)var + BNEPS);
    }
}

// ---------------- GAT aggregation v2 (warp/node, grid.y=layer) ----------------
// Fast path (deg<=32): single pass — each lane owns one edge's logits, warp-max,
// lane-parallel exp, smem-staged (src,exps), feature-parallel accumulation.
__global__ void gat_agg_kernel(const int* __restrict__ rowptr, const int* __restrict__ csrc,
                               const float* __restrict__ as_all, const float* __restrict__ ad_all,
                               const __half2* __restrict__ h_all, const float* __restrict__ gb_all,
                               float* __restrict__ out_all) {
    int layer = blockIdx.y;
    const float* a_s = as_all + (size_t)layer * NN * HH;
    const float* a_d = ad_all + (size_t)layer * NN * HH;
    const __half2* h = h_all + (size_t)layer * NN * (HF / 2);
    const float* gb = gb_all + (size_t)layer * HF;
    float* outx = out_all + (size_t)layer * NN * HF;

    __shared__ float smE[8][32][4];
    __shared__ int   smS[8][32];

    int gwarp = (blockIdx.x * blockDim.x + threadIdx.x) >> 5;
    int lane = threadIdx.x & 31;
    int wid = (threadIdx.x >> 5);
    if (gwarp >= NN) return;
    int d = gwarp;
    int beg = rowptr[d], end = rowptr[d + 1];
    int deg = end - beg;

    float4 ad4 = *(const float4*)(a_d + (size_t)d * 4);
    float4 sf4 = *(const float4*)(a_s + (size_t)d * 4);
    float self0 = lrelu(sf4.x + ad4.x);
    float self1 = lrelu(sf4.y + ad4.y);
    float self2 = lrelu(sf4.z + ad4.z);
    float self3 = lrelu(sf4.w + ad4.w);

    float ax[4], ay[4];
    float den0, den1, den2, den3;

    if (deg <= 32) {
        // ---- single pass ----
        int sl = 0;
        float l0 = -1e30f, l1 = -1e30f, l2 = -1e30f, l3 = -1e30f;
        bool active = lane < deg;
        if (active) {
            sl = csrc[beg + lane];
            float4 s4 = *(const float4*)(a_s + (size_t)sl * 4);
            l0 = lrelu(s4.x + ad4.x);
            l1 = lrelu(s4.y + ad4.y);
            l2 = lrelu(s4.z + ad4.z);
            l3 = lrelu(s4.w + ad4.w);
        }
        float m0 = fmaxf(l0, self0), m1 = fmaxf(l1, self1);
        float m2 = fmaxf(l2, self2), m3 = fmaxf(l3, self3);
#pragma unroll
        for (int o = 16; o; o >>= 1) {
            m0 = fmaxf(m0, __shfl_xor_sync(0xffffffffu, m0, o));
            m1 = fmaxf(m1, __shfl_xor_sync(0xffffffffu, m1, o));
            m2 = fmaxf(m2, __shfl_xor_sync(0xffffffffu, m2, o));
            m3 = fmaxf(m3, __shfl_xor_sync(0xffffffffu, m3, o));
        }
        float x0 = active ? expf(l0 - m0) : 0.f;
        float x1 = active ? expf(l1 - m1) : 0.f;
        float x2 = active ? expf(l2 - m2) : 0.f;
        float x3 = active ? expf(l3 - m3) : 0.f;
        // denominators: self + warp sum of edge exps
        float t0 = x0, t1 = x1, t2 = x2, t3 = x3;
#pragma unroll
        for (int o = 16; o; o >>= 1) {
            t0 += __shfl_xor_sync(0xffffffffu, t0, o);
            t1 += __shfl_xor_sync(0xffffffffu, t1, o);
            t2 += __shfl_xor_sync(0xffffffffu, t2, o);
            t3 += __shfl_xor_sync(0xffffffffu, t3, o);
        }
        float es0 = expf(self0 - m0), es1 = expf(self1 - m1);
        float es2 = expf(self2 - m2), es3 = expf(self3 - m3);
        den0 = es0 + t0; den1 = es1 + t1; den2 = es2 + t2; den3 = es3 + t3;
        // stage edges
        smS[wid][lane] = sl;
        smE[wid][lane][0] = x0; smE[wid][lane][1] = x1;
        smE[wid][lane][2] = x2; smE[wid][lane][3] = x3;
        __syncwarp();
        // self contribution
        {
            float ee[4] = {es0, es1, es2, es3};
            const __half2* hp = h + (size_t)d * (HF / 2);
#pragma unroll
            for (int j = 0; j < 4; j++) {
                float2 f = __half22float2(hp[j * 32 + lane]);
                ax[j] = ee[j] * f.x;
                ay[j] = ee[j] * f.y;
            }
        }
        for (int i = 0; i < deg; i++) {
            float4 ee4 = *(float4*)smE[wid][i];
            int s = smS[wid][i];
            float ee[4] = {ee4.x, ee4.y, ee4.z, ee4.w};
            const __half2* hp = h + (size_t)s * (HF / 2);
#pragma unroll
            for (int j = 0; j < 4; j++) {
                float2 f = __half22float2(hp[j * 32 + lane]);
                ax[j] += ee[j] * f.x;
                ay[j] += ee[j] * f.y;
            }
        }
    } else {
        // ---- fallback: two-pass chunked (rare) ----
        float m0 = self0, m1 = self1, m2 = self2, m3 = self3;
        for (int e = beg + lane; e < end; e += 32) {
            int s = csrc[e];
            float4 s4 = *(const float4*)(a_s + (size_t)s * 4);
            m0 = fmaxf(m0, lrelu(s4.x + ad4.x));
            m1 = fmaxf(m1, lrelu(s4.y + ad4.y));
            m2 = fmaxf(m2, lrelu(s4.z + ad4.z));
            m3 = fmaxf(m3, lrelu(s4.w + ad4.w));
        }
#pragma unroll
        for (int o = 16; o; o >>= 1) {
            m0 = fmaxf(m0, __shfl_xor_sync(0xffffffffu, m0, o));
            m1 = fmaxf(m1, __shfl_xor_sync(0xffffffffu, m1, o));
            m2 = fmaxf(m2, __shfl_xor_sync(0xffffffffu, m2, o));
            m3 = fmaxf(m3, __shfl_xor_sync(0xffffffffu, m3, o));
        }
        {
            float e0 = expf(self0 - m0), e1 = expf(self1 - m1);
            float e2 = expf(self2 - m2), e3 = expf(self3 - m3);
            den0 = e0; den1 = e1; den2 = e2; den3 = e3;
            float ee[4] = {e0, e1, e2, e3};
            const __half2* hp = h + (size_t)d * (HF / 2);
#pragma unroll
            for (int j = 0; j < 4; j++) {
                float2 f = __half22float2(hp[j * 32 + lane]);
                ax[j] = ee[j] * f.x;
                ay[j] = ee[j] * f.y;
            }
        }
        for (int c0 = beg; c0 < end; c0 += 32) {
            int e = c0 + lane;
            int sl = 0;
            float x0 = 0.f, x1 = 0.f, x2 = 0.f, x3 = 0.f;
            if (e < end) {
                sl = csrc[e];
                float4 s4 = *(const float4*)(a_s + (size_t)sl * 4);
                x0 = expf(lrelu(s4.x + ad4.x) - m0);
                x1 = expf(lrelu(s4.y + ad4.y) - m1);
                x2 = expf(lrelu(s4.z + ad4.z) - m2);
                x3 = expf(lrelu(s4.w + ad4.w) - m3);
            }
            smS[wid][lane] = sl;
            smE[wid][lane][0] = x0; smE[wid][lane][1] = x1;
            smE[wid][lane][2] = x2; smE[wid][lane][3] = x3;
            __syncwarp();
            int cnt = min(32, end - c0);
            for (int i = 0; i < cnt; i++) {
                float4 ee4 = *(float4*)smE[wid][i];
                int s = smS[wid][i];
                den0 += ee4.x; den1 += ee4.y; den2 += ee4.z; den3 += ee4.w;
                float ee[4] = {ee4.x, ee4.y, ee4.z, ee4.w};
                const __half2* hp = h + (size_t)s * (HF / 2);
#pragma unroll
                for (int j = 0; j < 4; j++) {
                    float2 f = __half22float2(hp[j * 32 + lane]);
                    ax[j] += ee[j] * f.x;
                    ay[j] += ee[j] * f.y;
                }
            }
            __syncwarp();
        }
    }

    float den[4] = {den0, den1, den2, den3};
    float* op = outx + (size_t)d * HF;
#pragma unroll
    for (int j = 0; j < 4; j++) {
        int c0 = 2 * (j * 32 + lane);
        float inv = 1.f / den[j];
        float ox = elu(ax[j] * inv + gb[c0]);
        float oy = elu(ay[j] * inv + gb[c0 + 1]);
        *(float2*)(op + c0) = make_float2(ox, oy);
    }
}

// ---------------- fused BN apply + residual + pool ----------------
__global__ void bnpool_kernel(const float* __restrict__ x, const float* __restrict__ z_all,
                              const float* __restrict__ g_all, const float* __restrict__ beta_all,
                              const float* __restrict__ mu_all, const float* __restrict__ rstd_all,
                              const int* __restrict__ batch, float* __restrict__ pooled) {
    int idx = blockIdx.x * blockDim.x + threadIdx.x;
    if (idx >= NN * FF) return;
    int n = idx >> 6, f = idx & 63;
    float v = x[idx];
#pragma unroll
    for (int i = 0; i < 4; i++) {
        float zz = z_all[(size_t)i * NN * FF + idx];
        v += (zz - mu_all[i * FF + f]) * rstd_all[i * FF + f] * g_all[i * FF + f]
             + beta_all[i * FF + f];
    }
    atomicAdd(&pooled[batch[n] * FF + f], v);
}

// ---------------- tiny FC + BN head ----------------
__global__ void fcbn_kernel(const float* __restrict__ A, const float* __restrict__ W,
                            const float* __restrict__ b, const float* __restrict__ g,
                            const float* __restrict__ beta, float* __restrict__ out,
                            int K, int Nc, int do_relu) {
    int j = blockIdx.x;
    int r = threadIdx.x;
    float y = b[j];
    for (int k = 0; k < K; k++) y += A[r * K + k] * W[k * Nc + j];
    __shared__ float sh[GG];
    __shared__ float s_mu, s_var;
    sh[r] = y;
    __syncthreads();
    if (r == 0) {
        float s = 0.f;
        for (int i = 0; i < GG; i++) s += sh[i];
        float mu = s / GG;
        float q = 0.f;
        for (int i = 0; i < GG; i++) { float dd = sh[i] - mu; q += dd * dd; }
        s_mu = mu; s_var = q / GG;
    }
    __syncthreads();
    float o = (y - s_mu) * rsqrtf(s_var + BNEPS) * g[j] + beta[j];
    if (do_relu) o = fmaxf(o, 0.f);
    out[r * Nc + j] = o;
}

// ---------------- launch ----------------
static inline void* sym(const void* s) {
    void* p = nullptr;
    cudaGetSymbolAddress(&p, s);
    return p;
}

extern "C" void kernel_launch(void* const* d_in, const int* in_sizes, int n_in,
                              void* d_out, int out_size) {
    const float* x       = (const float*)d_in[0];
    const int*  eidx     = (const int*)d_in[1];
    const int*  batch    = (const int*)d_in[2];
    const int*  sidx     = (const int*)d_in[3];
    const float* sattr   = (const float*)d_in[4];
    const float* gat_W   = (const float*)d_in[5];
    const float* gat_as  = (const float*)d_in[6];
    const float* gat_ad  = (const float*)d_in[7];
    const float* gat_b   = (const float*)d_in[8];
    const float* mlp_W   = (const float*)d_in[9];
    const float* mlp_b   = (const float*)d_in[10];
    const float* mlp_g   = (const float*)d_in[11];
    const float* mlp_be  = (const float*)d_in[12];
    const float* fc1_W   = (const float*)d_in[13];
    const float* fc1_b   = (const float*)d_in[14];
    const float* fc1_g   = (const float*)d_in[15];
    const float* fc1_be  = (const float*)d_in[16];
    const float* fc2_W   = (const float*)d_in[17];
    const float* fc2_b   = (const float*)d_in[18];
    const float* fc2_g   = (const float*)d_in[19];
    const float* fc2_be  = (const float*)d_in[20];
    const float* fc3_W   = (const float*)d_in[21];
    const float* fc3_b   = (const float*)d_in[22];
    const float* fc3_g   = (const float*)d_in[23];
    const float* fc3_be  = (const float*)d_in[24];
    float* out = (float*)d_out;

    float*   p_xs     = (float*)sym(d_xs);
    float*   p_xh     = (float*)sym(d_xh);
    __half2* p_h      = (__half2*)sym(d_h);
    float*   p_as     = (float*)sym(d_as);
    float*   p_ad     = (float*)sym(d_ad);
    float*   p_gacc   = (float*)sym(d_gacc);
    float*   p_z      = (float*)sym(d_z);
    float*   p_bnpart = (float*)sym(d_bnpart);
    float*   p_bnmu   = (float*)sym(d_bnmu);
    float*   p_bnrstd = (float*)sym(d_bnrstd);
    float*   p_pooled = (float*)sym(d_pooled);
    float*   p_h1     = (float*)sym(d_h1);
    float*   p_h2     = (float*)sym(d_h2);
    int*     p_cnt    = (int*)sym(d_cnt);
    int*     p_rowptr = (int*)sym(d_rowptr);
    int2*    p_cedge  = (int2*)sym(d_cedge);
    int*     p_csrc4  = (int*)sym(d_csrc4);

    const int TB = 256;
    const int EB = (ESZ + TB - 1) / TB;
    const int NW = (NN * 32 + TB - 1) / TB;

    // ---- batched CSR build (5 graphs) ----
    zero_i_kernel<<<(10 * NN + TB - 1) / TB, TB>>>(p_cnt, 10 * NN);
    hist5_kernel<<<dim3(EB, 5), TB>>>(sidx, eidx, p_cnt);
    scan5_kernel<<<5, 1024>>>(p_cnt, p_rowptr);
    fill5_kernel<<<dim3(EB, 5), TB>>>(sidx, eidx, sattr, p_rowptr, p_cnt, p_cedge, p_csrc4);

    // ---- solo passes (gather form) ----
    gatherA_kernel<<<dim3(NW, 4), TB>>>(p_rowptr, p_cedge, x, p_xs, p_xh);
    gather3_kernel<<<NW, TB>>>(p_rowptr, p_cedge,
                               p_xh, p_xh + (size_t)NN * FF, p_xh + (size_t)2 * NN * FF,
                               p_xs + (size_t)NN * FF, p_xs + (size_t)2 * NN * FF,
                               p_xs + (size_t)3 * NN * FF);

    // ---- batched GEMM1 + fused a_s/a_d (all 4 layers) ----
    gemm_asad_kernel<<<dim3((NN / 128) * 4, 1, 4), TB>>>(p_xs, gat_W, p_h, gat_as, gat_ad,
                                                         p_as, p_ad);

    // ---- GAT aggregation, all 4 layers in one launch ----
    const int* gat_rp = p_rowptr + (size_t)4 * (NN + 1);
    gat_agg_kernel<<<dim3(NW, 4), TB>>>(gat_rp, p_csrc4, p_as, p_ad, p_h, gat_b, p_gacc);

    // ---- batched GEMM2 + fused BN partials ----
    gemm_bn_kernel<<<dim3(NN / 128, 1, 4), TB>>>(p_gacc, mlp_W, mlp_b, p_z, p_bnpart);
    bnstat2_kernel<<<4, 256>>>(p_bnpart, p_bnmu, p_bnrstd);

    // ---- fused BN apply + residual + pool ----
    zero_f_kernel<<<(GG * FF / 4 + TB - 1) / TB, TB>>>((float4*)p_pooled, GG * FF / 4);
    bnpool_kernel<<<(NN * FF + TB - 1) / TB, TB>>>(x, p_z, mlp_g, mlp_be, p_bnmu, p_bnrstd,
                                                   batch, p_pooled);

    // ---- FC head ----
    fcbn_kernel<<<256, GG>>>(p_pooled, fc1_W, fc1_b, fc1_g, fc1_be, p_h1, 64, 256, 1);
    fcbn_kernel<<<128, GG>>>(p_h1, fc2_W, fc2_b, fc2_g, fc2_be, p_h2, 256, 128, 1);
    fcbn_kernel<<<NCLS, GG>>>(p_h2, fc3_W, fc3_b, fc3_g, fc3_be, out, 128, NCLS, 0);
}